// round 17
// baseline (speedup 1.0000x reference)
#include <cuda_runtime.h>
#include <cuda_fp16.h>
#include <cstdint>

#define B_   4
#define M_   65536
#define N_   16384
#define D_   128

#define OFF_IDX 0
#define OFF_SA  1024              // w tile  [64k][272B]
#define OFF_SB  (1024 + 17408)    // x tile  [64k][272B]
#define SMEM_F  (1024 + 2 * 17408)      // 35840
#define OFF_STG 1024              // stage [64tok][132w] fp32 (aliases SA+SB)
#define TPITCH  132
#define PITCHB  272

__device__ __half g_Z[(size_t)B_ * N_ * D_];   // 16 MB scratch [b][n][d], f16
__device__ __half g_wpre[64 * D_];             // w[0:64) as f16 [k][d]
__device__ int g_idx_is64;

// ---------------- helpers ----------------
static __device__ __forceinline__ uint32_t s2u(const void* p) {
    uint32_t a;
    asm("{ .reg .u64 t; cvta.to.shared.u64 t, %1; cvt.u32.u64 %0, t; }" : "=r"(a) : "l"(p));
    return a;
}
static __device__ __forceinline__ uint32_t pk(float lo, float hi) {
    uint32_t r;
    asm("cvt.rn.f16x2.f32 %0, %1, %2;" : "=r"(r) : "f"(hi), "f"(lo));
    return r;
}
static __device__ __forceinline__ void mma_f16(float* c, const uint32_t* a,
                                               uint32_t b0, uint32_t b1) {
    asm volatile(
        "mma.sync.aligned.m16n8k16.row.col.f32.f16.f16.f32 "
        "{%0,%1,%2,%3}, {%4,%5,%6,%7}, {%8,%9}, {%0,%1,%2,%3};"
        : "+f"(c[0]), "+f"(c[1]), "+f"(c[2]), "+f"(c[3])
        : "r"(a[0]), "r"(a[1]), "r"(a[2]), "r"(a[3]), "r"(b0), "r"(b1));
}
#define LDSM4T(r0, r1, r2, r3, a) \
    asm volatile("ldmatrix.sync.aligned.m8n8.x4.trans.shared.b16 {%0,%1,%2,%3}, [%4];" \
                 : "=r"(r0), "=r"(r1), "=r"(r2), "=r"(r3) : "r"(a))
#define LDSM2T(r0, r1, a) \
    asm volatile("ldmatrix.sync.aligned.m8n8.x2.trans.shared.b16 {%0,%1}, [%2];" \
                 : "=r"(r0), "=r"(r1) : "r"(a))
#define CP_ASYNC16(dst_u32, src_ptr) \
    asm volatile("cp.async.cg.shared.global [%0], [%1], 16;" :: "r"(dst_u32), "l"(src_ptr))
#define CP_COMMIT() asm volatile("cp.async.commit_group;" ::: "memory")
#define CP_WAIT0()  asm volatile("cp.async.wait_group 0;" ::: "memory")
#define GDC_LAUNCH() asm volatile("griddepcontrol.launch_dependents;")
#define GDC_WAIT()   asm volatile("griddepcontrol.wait;" ::: "memory")

// convert 64 rows x (C4*4) fp32 cols -> f16 tile [k][col]; NTH threads; optional streaming ld
template <int C4, int NTH, bool STREAM>
static __device__ __forceinline__ void conv_tile(char* smc, int offs,
                                                 const float* __restrict__ src,
                                                 size_t stride, int t) {
#pragma unroll
    for (int idx = t, it = 0; it < 64 * C4 / NTH; it++, idx += NTH) {
        int k = idx / C4, c = idx % C4;
        const float4* p = (const float4*)(src + (size_t)k * stride + c * 4);
        float4 v = STREAM ? __ldcs(p) : *p;
        uint2 u = make_uint2(pk(v.x, v.y), pk(v.z, v.w));
        *(uint2*)(smc + offs + k * PITCHB + c * 8) = u;
    }
}

// mainloop: warp tile 64d x 32tok over one K=64 chunk (64 MMAs)
static __device__ __forceinline__ void compute_chunk(uint32_t sb, int wm, int wn, int lane,
                                                     float acc[4][4][4]) {
    const int aRow = (lane & 7) | ((lane & 16) >> 1);
    const int aCol = (lane & 8);
    const int bRow = lane & 15;
#pragma unroll
    for (int ks = 0; ks < 4; ks++) {
        uint32_t A[4][4];
#pragma unroll
        for (int mt = 0; mt < 4; mt++)
            LDSM4T(A[mt][0], A[mt][1], A[mt][2], A[mt][3],
                   sb + OFF_SA + (ks * 16 + aRow) * PITCHB +
                       (wm * 64 + mt * 16 + aCol) * 2);
        uint32_t Bf[4][2];
#pragma unroll
        for (int nt = 0; nt < 4; nt++)
            LDSM2T(Bf[nt][0], Bf[nt][1],
                   sb + OFF_SB + (ks * 16 + bRow) * PITCHB + (wn * 32 + nt * 8) * 2);
#pragma unroll
        for (int mt = 0; mt < 4; mt++)
#pragma unroll
            for (int nt = 0; nt < 4; nt++)
                mma_f16(acc[mt][nt], A[mt], Bf[nt][0], Bf[nt][1]);
    }
}

// ================= GEMM 1 (256 thr, 128-token tile) =================
static __device__ __forceinline__ void stage_half(char* smc, int wm, int wn, int lane,
                                                  float acc[4][4][4], int h) {
    if ((wn >> 1) != h) return;
    float* stg = (float*)(smc + OFF_STG);
    const int r = lane >> 2, q2 = (lane & 3) * 2;
    const int tbase = (wn & 1) * 32;
#pragma unroll
    for (int mt = 0; mt < 4; mt++)
#pragma unroll
        for (int nt = 0; nt < 4; nt++) {
            int d = wm * 64 + mt * 16 + r;
            int tk = tbase + nt * 8 + q2;
            stg[tk * TPITCH + d]           = acc[mt][nt][0];
            stg[(tk + 1) * TPITCH + d]     = acc[mt][nt][1];
            stg[tk * TPITCH + d + 8]       = acc[mt][nt][2];
            stg[(tk + 1) * TPITCH + d + 8] = acc[mt][nt][3];
        }
}

__global__ void __launch_bounds__(256, 2) zgemm(const float* __restrict__ cur,
                                                const float* __restrict__ w,
                                                const void* __restrict__ up_idx) {
    extern __shared__ char smc[];
    uint32_t sb = s2u(smc);
    const int t = threadIdx.x, lane = t & 31, wid = t >> 5;
    const int wm = wid & 1, wn = wid >> 1;
    const int bb = blockIdx.y, tok0 = blockIdx.x * 128;

    if (blockIdx.x == 0 && blockIdx.y == 0) {
        // block 0 publishes g_wpre + idx flag BEFORE triggering dependent launch:
        // the PDL event (all blocks triggered) then orders these writes for fuse.
        if (t == 0) {
            const long long* p = (const long long*)up_idx;
            int ok = 1;
            for (int i = 0; i < 64; i++) {
                long long v = p[i];
                if (v < 0 || v >= N_) { ok = 0; break; }
            }
            g_idx_is64 = ok;
        }
#pragma unroll
        for (int i = 0; i < 8; i++) {
            int c = t + i * 256;
            float4 v = *(const float4*)(w + c * 4);
            *(uint2*)(g_wpre + c * 4) = make_uint2(pk(v.x, v.y), pk(v.z, v.w));
        }
        __threadfence();
        __syncthreads();
        GDC_LAUNCH();
    } else {
        GDC_LAUNCH();
    }

    float acc[4][4][4];
#pragma unroll
    for (int a = 0; a < 4; a++)
#pragma unroll
        for (int b = 0; b < 4; b++)
#pragma unroll
            for (int c = 0; c < 4; c++) acc[a][b][c] = 0.0f;

    const float* xb = cur + (size_t)bb * 128 * N_ + tok0;
#pragma unroll
    for (int c = 0; c < 2; c++) {
        conv_tile<32, 256, false>(smc, OFF_SA, w + (size_t)(64 + c * 64) * D_, D_, t);
        conv_tile<32, 256, true>(smc, OFF_SB, xb + (size_t)c * 64 * N_, N_, t);
        __syncthreads();
        compute_chunk(sb, wm, wn, lane, acc);
        __syncthreads();
    }

    const float* stg = (const float*)(smc + OFF_STG);
#pragma unroll
    for (int h = 0; h < 2; h++) {
        stage_half(smc, wm, wn, lane, acc, h);
        __syncthreads();
        __half* zb = g_Z + ((size_t)bb * N_ + tok0 + h * 64) * D_ + lane * 4;
#pragma unroll
        for (int i = 0; i < 8; i++) {
            int tok = wid * 8 + i;
            float4 v = *(const float4*)(stg + tok * TPITCH + lane * 4);
            *(uint2*)(zb + (size_t)tok * D_) = make_uint2(pk(v.x, v.y), pk(v.z, v.w));
        }
        __syncthreads();
    }
}

// ================= GEMM 2 + gather + BN + relu (128 thr, PDL secondary) ==============
static __device__ __forceinline__ void stage_acc(char* smc, int wm, int wn, int lane,
                                                 float acc[4][4][4]) {
    float* stg = (float*)(smc + OFF_STG);
    const int r = lane >> 2, q2 = (lane & 3) * 2;
#pragma unroll
    for (int mt = 0; mt < 4; mt++)
#pragma unroll
        for (int nt = 0; nt < 4; nt++) {
            int d = wm * 64 + mt * 16 + r;
            int tk = wn * 32 + nt * 8 + q2;
            stg[tk * TPITCH + d]           = acc[mt][nt][0];
            stg[(tk + 1) * TPITCH + d]     = acc[mt][nt][1];
            stg[tk * TPITCH + d + 8]       = acc[mt][nt][2];
            stg[(tk + 1) * TPITCH + d + 8] = acc[mt][nt][3];
        }
}

__global__ void __launch_bounds__(128, 4) fuse(const float* __restrict__ pre,
                                               const void* __restrict__ up_idx,
                                               const float* __restrict__ bias,
                                               const float* __restrict__ gamma,
                                               const float* __restrict__ beta,
                                               const float* __restrict__ rmean,
                                               const float* __restrict__ rvar,
                                               float* __restrict__ out) {
    extern __shared__ char smc[];
    uint32_t sb = s2u(smc);
    const int t = threadIdx.x, lane = t & 31, wid = t >> 5;
    const int wm = wid & 1, wn = wid >> 1;
    const int bb = blockIdx.y, tok0 = blockIdx.x * 64;

    // --- pre-wait phase: independent of g_Z ---
#pragma unroll
    for (int i = 0; i < 8; i++) {
        int c = t + i * 128;
        int k = c >> 4, j = c & 15;
        CP_ASYNC16(sb + OFF_SA + k * PITCHB + j * 16,
                   (const char*)(g_wpre + (size_t)k * D_) + j * 16);
    }
    CP_COMMIT();

    int* sIdx = (int*)(smc + OFF_IDX);
    if (t < 64) {
        size_t ip = (size_t)bb * M_ + tok0 + t;
        sIdx[t] = g_idx_is64 ? (int)((const long long*)up_idx)[ip]
                             : ((const int*)up_idx)[ip];
    }

    float acc[4][4][4];
#pragma unroll
    for (int a = 0; a < 4; a++)
#pragma unroll
        for (int b = 0; b < 4; b++)
#pragma unroll
            for (int c = 0; c < 4; c++) acc[a][b][c] = 0.0f;

    conv_tile<16, 128, true>(smc, OFF_SB, pre + (size_t)bb * 64 * M_ + tok0, M_, t);
    CP_WAIT0();
    __syncthreads();
    compute_chunk(sb, wm, wn, lane, acc);
    __syncthreads();
    stage_acc(smc, wm, wn, lane, acc);

    // per-lane BN fold for d = lane*4 .. lane*4+3
    float4 s4, t4;
    {
        int d0 = lane * 4;
        float4 rv = *(const float4*)(rvar + d0);
        float4 gm = *(const float4*)(gamma + d0);
        float4 bi = *(const float4*)(bias + d0);
        float4 rm = *(const float4*)(rmean + d0);
        float4 be = *(const float4*)(beta + d0);
        s4.x = rsqrtf(rv.x + 1e-5f) * gm.x;
        s4.y = rsqrtf(rv.y + 1e-5f) * gm.y;
        s4.z = rsqrtf(rv.z + 1e-5f) * gm.z;
        s4.w = rsqrtf(rv.w + 1e-5f) * gm.w;
        t4.x = (bi.x - rm.x) * s4.x + be.x;
        t4.y = (bi.y - rm.y) * s4.y + be.y;
        t4.z = (bi.z - rm.z) * s4.z + be.z;
        t4.w = (bi.w - rm.w) * s4.w + be.w;
    }
    __syncthreads();

    // --- wait for zgemm's Z to be complete & visible, then gather via L2 ---
    GDC_WAIT();

    const float* stg = (const float*)(smc + OFF_STG);
    const __half* zB = g_Z + (size_t)bb * N_ * D_ + lane * 4;
    float* ob = out + ((size_t)bb * M_ + tok0) * D_ + lane * 4;

#pragma unroll
    for (int h = 0; h < 2; h++) {
        uint2 zr[8];
#pragma unroll
        for (int i = 0; i < 8; i++)
            zr[i] = __ldcg((const uint2*)(zB + (size_t)sIdx[wid * 16 + h * 8 + i] * D_));
#pragma unroll
        for (int i = 0; i < 8; i++) {
            int tok = wid * 16 + h * 8 + i;
            float4 a = *(const float4*)(stg + tok * TPITCH + lane * 4);
            float2 z0 = __half22float2(*(const __half2*)&zr[i].x);
            float2 z1 = __half22float2(*(const __half2*)&zr[i].y);
            float4 v;
            v.x = fmaxf((a.x + z0.x) * s4.x + t4.x, 0.0f);
            v.y = fmaxf((a.y + z0.y) * s4.y + t4.y, 0.0f);
            v.z = fmaxf((a.z + z1.x) * s4.z + t4.z, 0.0f);
            v.w = fmaxf((a.w + z1.y) * s4.w + t4.w, 0.0f);
            __stcs((float4*)(ob + (size_t)tok * D_), v);
        }
    }
}

extern "C" void kernel_launch(void* const* d_in, const int* in_sizes, int n_in,
                              void* d_out, int out_size) {
    const float* pre_x  = (const float*)d_in[0];
    const float* cur_x  = (const float*)d_in[1];
    const void*  up_idx = d_in[2];
    const float* w      = (const float*)d_in[3];
    const float* bias   = (const float*)d_in[4];
    const float* gamma  = (const float*)d_in[5];
    const float* beta   = (const float*)d_in[6];
    const float* rmean  = (const float*)d_in[7];
    const float* rvar   = (const float*)d_in[8];
    float* out = (float*)d_out;

    cudaFuncSetAttribute(zgemm, cudaFuncAttributeMaxDynamicSharedMemorySize, SMEM_F);
    cudaFuncSetAttribute(fuse, cudaFuncAttributeMaxDynamicSharedMemorySize, SMEM_F);

    zgemm<<<dim3(N_ / 128, B_), 256, SMEM_F>>>(cur_x, w, up_idx);

    // fuse as PDL secondary: launches while zgemm drains; waits before the Z gather.
    cudaLaunchConfig_t cfg = {};
    cfg.gridDim = dim3(M_ / 64, B_);
    cfg.blockDim = dim3(128);
    cfg.dynamicSmemBytes = SMEM_F;
    cfg.stream = 0;
    cudaLaunchAttribute attrs[1];
    attrs[0].id = cudaLaunchAttributeProgrammaticStreamSerialization;
    attrs[0].val.programmaticStreamSerializationAllowed = 1;
    cfg.attrs = attrs;
    cfg.numAttrs = 1;
    cudaLaunchKernelEx(&cfg, fuse, pre_x, up_idx, bias, gamma, beta, rmean, rvar, out);
}